// round 12
// baseline (speedup 1.0000x reference)
#include <cuda_runtime.h>
#include <cstdint>

// Problem constants
#define BB 32
#define CC 256
#define DD 768

// Tiling
#define DTILE 128                  // d rows per CTA (16 per warp x 8 warps)
#define KSTEP 32                   // e columns per pipeline stage
#define NDTILES (DD / DTILE)       // 6  -> grid = CC * NDTILES = 1536 CTAs
#define KSTAGES (DD / KSTEP)       // 24 stages per CTA
#define SBUF 6                     // per-warp ring depth
#define LOOKAHEAD 5                // stages issued ahead

#define WROWS 16                   // d rows per warp
#define LSTG 36                    // stage row stride (words); 36%32==4 -> conflict-free A LDS
#define WSTG (WROWS * LSTG)        // 576 words / stage / warp
#define LDIFF 772                  // diff row stride (words); 772%32==4 -> conflict-free B LDS.128

#define DIFF_SZ (BB * LDIFF)                            // 24704 words
#define SMEM_WORDS (DIFF_SZ + 8 * SBUF * WSTG + 256)    // ~210.4 KB

#define NITEMS (CC * NDTILES)      // 1536

// e-permutation within each 32-block: groups e%4 together so that the
// {q, q+4, q+8, ...} TF32 B-fragment elements become contiguous (LDS.128-able).
#define PERM(e) (((e) & ~31) | (((e) & 3) << 3) | (((e) >> 2) & 7))

// Partial dist sums: [class][dtile][b]
__device__ float g_partial[CC * NDTILES * BB];

__device__ __forceinline__ uint32_t f2tf(float f) {
    uint32_t r;
    asm("cvt.rna.tf32.f32 %0, %1;\n" : "=r"(r) : "f"(f));
    return r;
}

__device__ __forceinline__ void mma_tf32(float* c,
                                         uint32_t a0, uint32_t a1, uint32_t a2, uint32_t a3,
                                         uint32_t b0, uint32_t b1) {
    asm volatile(
        "mma.sync.aligned.m16n8k8.row.col.f32.tf32.tf32.f32 "
        "{%0,%1,%2,%3}, {%4,%5,%6,%7}, {%8,%9}, {%0,%1,%2,%3};\n"
        : "+f"(c[0]), "+f"(c[1]), "+f"(c[2]), "+f"(c[3])
        : "r"(a0), "r"(a1), "r"(a2), "r"(a3), "r"(b0), "r"(b1));
}

__device__ __forceinline__ void cp_async16(float* sdst, const float* gsrc) {
    unsigned saddr = (unsigned)__cvta_generic_to_shared(sdst);
    asm volatile("cp.async.cg.shared.global [%0], [%1], 16;\n"
                 :: "r"(saddr), "l"(gsrc));
}
__device__ __forceinline__ void cp_commit() {
    asm volatile("cp.async.commit_group;\n" ::: "memory");
}

// Warp-private stage load: this warp's 16 rows x 32 cols of the CTA's M slab.
// 64 x 16B chunks, 4 per lane; 8 lanes cover one 128B gmem line.
__device__ __forceinline__ void issue_stage_w(const float* __restrict__ Mslab,
                                              float* __restrict__ wstg,
                                              int ks, int lane) {
    const float* base = Mslab + ks * KSTEP;
    float* dst = wstg + (ks % SBUF) * WSTG;
#pragma unroll
    for (int j = 0; j < 4; j++) {
        int idx = lane + 32 * j;      // 0..127
        int r   = idx >> 3;           // 0..15
        int c4  = (idx & 7) << 2;     // 0,4,...,28
        cp_async16(dst + r * LSTG + c4, base + (size_t)r * DD + c4);
    }
    cp_commit();
}

__global__ void __launch_bounds__(256, 1)
fecam_score_kernel(const float* __restrict__ x,      // [32,768]
                   const float* __restrict__ mu,     // [256,768]
                   const float* __restrict__ g,      // [256,768]
                   const float* __restrict__ Minv)   // [256,768,768]
{
    extern __shared__ float smem[];
    float* sdiff = smem;                               // [32][772], e-permuted, tf32-rounded
    float* sstg  = smem + DIFF_SZ;                     // 8 x SBUF x [16][36]
    float* sred  = smem + DIFF_SZ + 8 * SBUF * WSTG;   // [8][32]

    const int item = blockIdx.x;
    const int c    = item / NDTILES;
    const int dt   = item - c * NDTILES;
    const int tid  = threadIdx.x;
    const int w    = tid >> 5;
    const int lane = tid & 31;
    const int grp  = lane >> 2;   // 0..7
    const int q    = lane & 3;    // 0..3

    // This CTA's M slab: rows [dt*128, dt*128+128); this warp's 16-row sub-slab.
    const float* Mslab = Minv + (size_t)c * DD * DD
                              + (size_t)(dt * DTILE + w * WROWS) * DD;
    float* wstg = sstg + w * (SBUF * WSTG);

    // ---- Prologue: start streaming M before anything else ----
#pragma unroll
    for (int p = 0; p < LOOKAHEAD; p++)
        issue_stage_w(Mslab, wstg, p, lane);

    // ---- Phase 1: diff[b][e] = (x[b][e]-mu[c][e])/g[c][e], TF32-rounded,
    //      stored e-permuted in smem ----
    {
        float rcp[3], mun[3];
        int   pe[3];
#pragma unroll
        for (int i = 0; i < 3; i++) {
            int e = tid + i * 256;
            float gg = g[(size_t)c * DD + e];
            rcp[i] = 1.0f / gg;
            mun[i] = mu[(size_t)c * DD + e] * rcp[i];
            pe[i]  = PERM(e);
        }
        for (int b = 0; b < BB; b++) {
#pragma unroll
            for (int i = 0; i < 3; i++) {
                int e = tid + i * 256;
                float d = x[b * DD + e] * rcp[i] - mun[i];
                sdiff[b * LDIFF + pe[i]] = __uint_as_float(f2tf(d));
            }
        }
    }
    __syncthreads();

    // Accumulators: warp owns d rows [dt*128 + w*16, +16), all 32 batch cols.
    float acc[4][4];
#pragma unroll
    for (int t = 0; t < 4; t++)
#pragma unroll
        for (int i = 0; i < 4; i++) acc[t][i] = 0.0f;

    // ---- Mainloop: 24 stages, per-warp cp.async pipeline, no CTA barriers ----
    for (int ks = 0; ks < KSTAGES; ks++) {
        asm volatile("cp.async.wait_group 4;\n" ::: "memory");
        __syncwarp();

        if (ks + LOOKAHEAD < KSTAGES) issue_stage_w(Mslab, wstg, ks + LOOKAHEAD, lane);
        else                          cp_commit();   // keep group-count invariant

        const float* stg = wstg + (ks % SBUF) * WSTG;

        // B fragments for all 4 n-tiles, all 4 k-steps: 8x LDS.128 (conflict-free)
        uint4 bv[4][2];
        {
            const float* dB = sdiff + ks * KSTEP + (q << 3);
#pragma unroll
            for (int t = 0; t < 4; t++) {
                const uint4* p = (const uint4*)(dB + (t * 8 + grp) * LDIFF);
                bv[t][0] = p[0];
                bv[t][1] = p[1];
            }
        }

#pragma unroll
        for (int kk = 0; kk < 4; kk++) {
            const float* ap = stg + grp * LSTG + kk * 8 + q;
            uint32_t a0 = f2tf(ap[0]);
            uint32_t a1 = f2tf(ap[8 * LSTG]);
            uint32_t a2 = f2tf(ap[4]);
            uint32_t a3 = f2tf(ap[8 * LSTG + 4]);
#pragma unroll
            for (int t = 0; t < 4; t++) {
                uint32_t b0, b1;
                if      (kk == 0) { b0 = bv[t][0].x; b1 = bv[t][0].y; }
                else if (kk == 1) { b0 = bv[t][0].z; b1 = bv[t][0].w; }
                else if (kk == 2) { b0 = bv[t][1].x; b1 = bv[t][1].y; }
                else              { b0 = bv[t][1].z; b1 = bv[t][1].w; }
                mma_tf32(acc[t], a0, a1, a2, a3, b0, b1);
            }
        }
    }

    // ---- Epilogue: fold u[b,d] into per-thread dist partials ----
    float part[8];
#pragma unroll
    for (int i = 0; i < 8; i++) part[i] = 0.0f;
    {
        const int dA  = dt * DTILE + (w << 4) + grp;
        const int pd0 = PERM(dA);
        const int pd1 = PERM(dA + 8);
#pragma unroll
        for (int t = 0; t < 4; t++) {
            const int b0i = t * 8 + (q << 1);
            part[2 * t]     += sdiff[b0i * LDIFF + pd0] * acc[t][0]
                             + sdiff[b0i * LDIFF + pd1] * acc[t][2];
            part[2 * t + 1] += sdiff[(b0i + 1) * LDIFF + pd0] * acc[t][1]
                             + sdiff[(b0i + 1) * LDIFF + pd1] * acc[t][3];
        }
    }

    // ---- Reduce: lanes sharing q hold the same b set; reduce over grp bits ----
#pragma unroll
    for (int i = 0; i < 8; i++) {
        part[i] += __shfl_xor_sync(0xffffffffu, part[i], 4);
        part[i] += __shfl_xor_sync(0xffffffffu, part[i], 8);
        part[i] += __shfl_xor_sync(0xffffffffu, part[i], 16);
    }
    if (lane < 4) {
#pragma unroll
        for (int t = 0; t < 4; t++) {
            sred[w * 32 + t * 8 + lane * 2]     = part[2 * t];
            sred[w * 32 + t * 8 + lane * 2 + 1] = part[2 * t + 1];
        }
    }
    __syncthreads();
    if (tid < BB) {
        float tot = 0.0f;
#pragma unroll
        for (int ww = 0; ww < 8; ww++) tot += sred[ww * 32 + tid];
        g_partial[item * BB + tid] = tot;   // dist partial for (c, dt), batch=tid
    }
}

// out[b][c] = -(sum over 6 d-tile partials)
__global__ void fecam_reduce_kernel(float* __restrict__ out) {
    int i = blockIdx.x * blockDim.x + threadIdx.x;   // i = b*CC + c
    if (i >= BB * CC) return;
    int b = i / CC;
    int c = i - b * CC;
    float tot = 0.0f;
#pragma unroll
    for (int dt = 0; dt < NDTILES; dt++)
        tot += g_partial[(c * NDTILES + dt) * BB + b];
    out[i] = -tot;
}

extern "C" void kernel_launch(void* const* d_in, const int* in_sizes, int n_in,
                              void* d_out, int out_size) {
    (void)in_sizes; (void)n_in; (void)out_size;
    const float* x  = (const float*)d_in[0];   // raw_features   [32,768]
    const float* mu = (const float*)d_in[1];   // class_means    [256,768]
    const float* g  = (const float*)d_in[2];   // class_diags    [256,768]
    const float* M  = (const float*)d_in[3];   // class_cov_invs [256,768,768]
    float* out = (float*)d_out;                // scores [32,256]

    const size_t smem_bytes = SMEM_WORDS * sizeof(float);   // ~210.4 KB
    cudaFuncSetAttribute(fecam_score_kernel,
                         cudaFuncAttributeMaxDynamicSharedMemorySize,
                         (int)smem_bytes);
    fecam_score_kernel<<<NITEMS, 256, smem_bytes>>>(x, mu, g, M);
    fecam_reduce_kernel<<<(BB * CC + 255) / 256, 256>>>(out);
}

// round 13
// speedup vs baseline: 1.0472x; 1.0472x over previous
#include <cuda_runtime.h>
#include <cstdint>

// Problem constants
#define BB 32
#define CC 256
#define DD 768

// Tiling
#define DTILE 128                  // d rows per CTA (16 per warp x 8 warps)
#define KSTEP 32                   // e columns per pipeline stage
#define NDTILES (DD / DTILE)       // 6  -> grid = CC * NDTILES = 1536 CTAs
#define KSTAGES (DD / KSTEP)       // 24 stages per CTA
#define SBUF 6                     // per-warp ring depth
#define LOOKAHEAD 5                // stages issued ahead

#define WROWS 16                   // d rows per warp
#define LSTG 36                    // stage row stride (words); 36%32==4 -> conflict-free A LDS
#define WSTG (WROWS * LSTG)        // 576 words / stage / warp
#define LDIFF 772                  // diff row stride (words); 772%32==4 -> conflict-free B LDS.128

#define DIFF_SZ (BB * LDIFF)                            // 24704 words
#define SMEM_WORDS (DIFF_SZ + 8 * SBUF * WSTG + 256)    // ~210.4 KB

#define NITEMS (CC * NDTILES)      // 1536

// e-permutation within each 32-block: groups e%4 together so that the
// {q, q+4, q+8, ...} TF32 B-fragment elements become contiguous (LDS.128-able).
#define PERM(e) (((e) & ~31) | (((e) & 3) << 3) | (((e) >> 2) & 7))

// Partial dist sums: [class][dtile][b]
__device__ float g_partial[CC * NDTILES * BB];

__device__ __forceinline__ uint32_t f2tf(float f) {
    uint32_t r;
    asm("cvt.rna.tf32.f32 %0, %1;\n" : "=r"(r) : "f"(f));
    return r;
}

__device__ __forceinline__ void mma_tf32(float* c,
                                         uint32_t a0, uint32_t a1, uint32_t a2, uint32_t a3,
                                         uint32_t b0, uint32_t b1) {
    asm volatile(
        "mma.sync.aligned.m16n8k8.row.col.f32.tf32.tf32.f32 "
        "{%0,%1,%2,%3}, {%4,%5,%6,%7}, {%8,%9}, {%0,%1,%2,%3};\n"
        : "+f"(c[0]), "+f"(c[1]), "+f"(c[2]), "+f"(c[3])
        : "r"(a0), "r"(a1), "r"(a2), "r"(a3), "r"(b0), "r"(b1));
}

__device__ __forceinline__ void cp_async16(float* sdst, const float* gsrc) {
    unsigned saddr = (unsigned)__cvta_generic_to_shared(sdst);
    asm volatile("cp.async.cg.shared.global [%0], [%1], 16;\n"
                 :: "r"(saddr), "l"(gsrc));
}
__device__ __forceinline__ void cp_commit() {
    asm volatile("cp.async.commit_group;\n" ::: "memory");
}

// Warp-private stage load: this warp's 16 rows x 32 cols of the CTA's M slab.
// 64 x 16B chunks, 4 per lane; 8 lanes cover one 128B gmem line.
__device__ __forceinline__ void issue_stage_w(const float* __restrict__ Mslab,
                                              float* __restrict__ wstg,
                                              int ks, int lane) {
    const float* base = Mslab + ks * KSTEP;
    float* dst = wstg + (ks % SBUF) * WSTG;
#pragma unroll
    for (int j = 0; j < 4; j++) {
        int idx = lane + 32 * j;      // 0..127
        int r   = idx >> 3;           // 0..15
        int c4  = (idx & 7) << 2;     // 0,4,...,28
        cp_async16(dst + r * LSTG + c4, base + (size_t)r * DD + c4);
    }
    cp_commit();
}

__global__ void __launch_bounds__(256, 1)
fecam_score_kernel(const float* __restrict__ x,      // [32,768]
                   const float* __restrict__ mu,     // [256,768]
                   const float* __restrict__ g,      // [256,768]
                   const float* __restrict__ Minv)   // [256,768,768]
{
    extern __shared__ float smem[];
    float* sdiff = smem;                               // [32][772], e-permuted, tf32-rounded
    float* sstg  = smem + DIFF_SZ;                     // 8 x SBUF x [16][36]
    float* sred  = smem + DIFF_SZ + 8 * SBUF * WSTG;   // [8][32]

    const int item = blockIdx.x;
    const int c    = item / NDTILES;
    const int dt   = item - c * NDTILES;
    const int tid  = threadIdx.x;
    const int w    = tid >> 5;
    const int lane = tid & 31;
    const int grp  = lane >> 2;   // 0..7
    const int q    = lane & 3;    // 0..3

    // This CTA's M slab: rows [dt*128, dt*128+128); this warp's 16-row sub-slab.
    const float* Mslab = Minv + (size_t)c * DD * DD
                              + (size_t)(dt * DTILE + w * WROWS) * DD;
    float* wstg = sstg + w * (SBUF * WSTG);

    // ---- Prologue: start streaming M before anything else ----
#pragma unroll
    for (int p = 0; p < LOOKAHEAD; p++)
        issue_stage_w(Mslab, wstg, p, lane);

    // ---- Phase 1: diff[b][e] = (x[b][e]-mu[c][e])/g[c][e], TF32-rounded,
    //      stored e-permuted in smem ----
    {
        float rcp[3], mun[3];
        int   pe[3];
#pragma unroll
        for (int i = 0; i < 3; i++) {
            int e = tid + i * 256;
            float gg = g[(size_t)c * DD + e];
            rcp[i] = 1.0f / gg;
            mun[i] = mu[(size_t)c * DD + e] * rcp[i];
            pe[i]  = PERM(e);
        }
        for (int b = 0; b < BB; b++) {
#pragma unroll
            for (int i = 0; i < 3; i++) {
                int e = tid + i * 256;
                float d = x[b * DD + e] * rcp[i] - mun[i];
                sdiff[b * LDIFF + pe[i]] = __uint_as_float(f2tf(d));
            }
        }
    }
    __syncthreads();

    // Accumulators: warp owns d rows [dt*128 + w*16, +16), all 32 batch cols.
    float acc[4][4];
#pragma unroll
    for (int t = 0; t < 4; t++)
#pragma unroll
        for (int i = 0; i < 4; i++) acc[t][i] = 0.0f;

    // ---- Mainloop: 24 stages, per-warp cp.async pipeline, no CTA barriers ----
    for (int ks = 0; ks < KSTAGES; ks++) {
        asm volatile("cp.async.wait_group 4;\n" ::: "memory");
        __syncwarp();

        if (ks + LOOKAHEAD < KSTAGES) issue_stage_w(Mslab, wstg, ks + LOOKAHEAD, lane);
        else                          cp_commit();   // keep group-count invariant

        const float* stg = wstg + (ks % SBUF) * WSTG;

        // B fragments for all 4 n-tiles, all 4 k-steps: 8x LDS.128 (conflict-free)
        uint4 bv[4][2];
        {
            const float* dB = sdiff + ks * KSTEP + (q << 3);
#pragma unroll
            for (int t = 0; t < 4; t++) {
                const uint4* p = (const uint4*)(dB + (t * 8 + grp) * LDIFF);
                bv[t][0] = p[0];
                bv[t][1] = p[1];
            }
        }

#pragma unroll
        for (int kk = 0; kk < 4; kk++) {
            const float* ap = stg + grp * LSTG + kk * 8 + q;
            uint32_t a0 = f2tf(ap[0]);
            uint32_t a1 = f2tf(ap[8 * LSTG]);
            uint32_t a2 = f2tf(ap[4]);
            uint32_t a3 = f2tf(ap[8 * LSTG + 4]);
#pragma unroll
            for (int t = 0; t < 4; t++) {
                uint32_t b0, b1;
                if      (kk == 0) { b0 = bv[t][0].x; b1 = bv[t][0].y; }
                else if (kk == 1) { b0 = bv[t][0].z; b1 = bv[t][0].w; }
                else if (kk == 2) { b0 = bv[t][1].x; b1 = bv[t][1].y; }
                else              { b0 = bv[t][1].z; b1 = bv[t][1].w; }
                mma_tf32(acc[t], a0, a1, a2, a3, b0, b1);
            }
        }
    }

    // ---- Epilogue: fold u[b,d] into per-thread dist partials ----
    float part[8];
#pragma unroll
    for (int i = 0; i < 8; i++) part[i] = 0.0f;
    {
        const int dA  = dt * DTILE + (w << 4) + grp;
        const int pd0 = PERM(dA);
        const int pd1 = PERM(dA + 8);
#pragma unroll
        for (int t = 0; t < 4; t++) {
            const int b0i = t * 8 + (q << 1);
            part[2 * t]     += sdiff[b0i * LDIFF + pd0] * acc[t][0]
                             + sdiff[b0i * LDIFF + pd1] * acc[t][2];
            part[2 * t + 1] += sdiff[(b0i + 1) * LDIFF + pd0] * acc[t][1]
                             + sdiff[(b0i + 1) * LDIFF + pd1] * acc[t][3];
        }
    }

    // ---- Reduce: lanes sharing q hold the same b set; reduce over grp bits ----
#pragma unroll
    for (int i = 0; i < 8; i++) {
        part[i] += __shfl_xor_sync(0xffffffffu, part[i], 4);
        part[i] += __shfl_xor_sync(0xffffffffu, part[i], 8);
        part[i] += __shfl_xor_sync(0xffffffffu, part[i], 16);
    }
    if (lane < 4) {
#pragma unroll
        for (int t = 0; t < 4; t++) {
            sred[w * 32 + t * 8 + lane * 2]     = part[2 * t];
            sred[w * 32 + t * 8 + lane * 2 + 1] = part[2 * t + 1];
        }
    }
    __syncthreads();
    if (tid < BB) {
        float tot = 0.0f;
#pragma unroll
        for (int ww = 0; ww < 8; ww++) tot += sred[ww * 32 + tid];
        g_partial[item * BB + tid] = tot;   // dist partial for (c, dt), batch=tid
    }
}

// out[b][c] = -(sum over 6 d-tile partials)
__global__ void fecam_reduce_kernel(float* __restrict__ out) {
    int i = blockIdx.x * blockDim.x + threadIdx.x;   // i = b*CC + c
    if (i >= BB * CC) return;
    int b = i / CC;
    int c = i - b * CC;
    float tot = 0.0f;
#pragma unroll
    for (int dt = 0; dt < NDTILES; dt++)
        tot += g_partial[(c * NDTILES + dt) * BB + b];
    out[i] = -tot;
}

extern "C" void kernel_launch(void* const* d_in, const int* in_sizes, int n_in,
                              void* d_out, int out_size) {
    (void)in_sizes; (void)n_in; (void)out_size;
    const float* x  = (const float*)d_in[0];   // raw_features   [32,768]
    const float* mu = (const float*)d_in[1];   // class_means    [256,768]
    const float* g  = (const float*)d_in[2];   // class_diags    [256,768]
    const float* M  = (const float*)d_in[3];   // class_cov_invs [256,768,768]
    float* out = (float*)d_out;                // scores [32,256]

    const size_t smem_bytes = SMEM_WORDS * sizeof(float);   // ~210.4 KB
    cudaFuncSetAttribute(fecam_score_kernel,
                         cudaFuncAttributeMaxDynamicSharedMemorySize,
                         (int)smem_bytes);
    fecam_score_kernel<<<NITEMS, 256, smem_bytes>>>(x, mu, g, M);
    fecam_reduce_kernel<<<(BB * CC + 255) / 256, 256>>>(out);
}

// round 14
// speedup vs baseline: 1.4316x; 1.3672x over previous
#include <cuda_runtime.h>
#include <cstdint>

// Problem constants
#define BB 32
#define CC 256
#define DD 768

// Tiling
#define DTILE 128                  // d rows per d-tile (16 per warp x 8 warps)
#define KSTEP 32                   // e columns per pipeline stage
#define NDTILES (DD / DTILE)       // 6
#define KSTAGES (DD / KSTEP)       // 24
#define NTOT (NDTILES * KSTAGES)   // 144 stages (order: s = ks*6 + dt)
#define SBUF 6                     // per-warp ring depth; buf == dt statically
#define LOOKAHEAD 5                // cp.async stages issued ahead
#define PFDIST 6                   // L2 prefetch distance beyond cp.async lookahead

#define WROWS 16                   // d rows per warp
#define LSTG 36                    // stage row stride (words); 36%32==4 -> conflict-free A LDS
#define WSTG (WROWS * LSTG)        // 576 words / stage / warp
#define LDIFF 772                  // diff row stride (words); 772%32==4 -> conflict-free B LDS.128

#define DIFF_SZ (BB * LDIFF)                            // 24704 words
#define SMEM_WORDS (DIFF_SZ + 8 * SBUF * WSTG + 256)    // ~210.4 KB

// e-permutation within each 32-block: groups e%4 together so that the
// {q, q+4, q+8, ...} TF32 B-fragment elements become contiguous (LDS.128-able).
#define PERM(e) (((e) & ~31) | (((e) & 3) << 3) | (((e) >> 2) & 7))

__device__ __forceinline__ uint32_t f2tf(float f) {
    uint32_t r;
    asm("cvt.rna.tf32.f32 %0, %1;\n" : "=r"(r) : "f"(f));
    return r;
}

__device__ __forceinline__ void mma_tf32(float* c,
                                         uint32_t a0, uint32_t a1, uint32_t a2, uint32_t a3,
                                         uint32_t b0, uint32_t b1) {
    asm volatile(
        "mma.sync.aligned.m16n8k8.row.col.f32.tf32.tf32.f32 "
        "{%0,%1,%2,%3}, {%4,%5,%6,%7}, {%8,%9}, {%0,%1,%2,%3};\n"
        : "+f"(c[0]), "+f"(c[1]), "+f"(c[2]), "+f"(c[3])
        : "r"(a0), "r"(a1), "r"(a2), "r"(a3), "r"(b0), "r"(b1));
}

__device__ __forceinline__ void cp_async16(float* sdst, const float* gsrc) {
    unsigned saddr = (unsigned)__cvta_generic_to_shared(sdst);
    asm volatile("cp.async.cg.shared.global [%0], [%1], 16;\n"
                 :: "r"(saddr), "l"(gsrc));
}
__device__ __forceinline__ void cp_commit() {
    asm volatile("cp.async.commit_group;\n" ::: "memory");
}
__device__ __forceinline__ void l2_prefetch(const float* p) {
    asm volatile("prefetch.global.L2 [%0];\n" :: "l"(p));
}

// Warp-private stage load: this warp's 16 rows x 32 cols of M for stage s
// (s = ks*6 + dt). Also fire-and-forget L2 prefetch of stage s+PFDIST:
// 16 lines (one per row), lanes 0-15, no smem / no tracking -> unbounded MLP.
__device__ __forceinline__ void issue_stage_w(const float* __restrict__ Mwarp,
                                              float* __restrict__ wstg,
                                              int s, int lane) {
    {
        const int dt = s % NDTILES;
        const int ks = s / NDTILES;
        const float* base = Mwarp + (size_t)(dt * DTILE) * DD + ks * KSTEP;
        float* dst = wstg + (s % SBUF) * WSTG;
#pragma unroll
        for (int j = 0; j < 4; j++) {
            int idx = lane + 32 * j;      // 0..127
            int r   = idx >> 3;           // 0..15
            int c4  = (idx & 7) << 2;     // 0,4,...,28
            cp_async16(dst + r * LSTG + c4, base + (size_t)r * DD + c4);
        }
        cp_commit();
    }
    const int spf = s + PFDIST;
    if (spf < NTOT && lane < WROWS) {
        const int dtp = spf % NDTILES;
        const int ksp = spf / NDTILES;
        l2_prefetch(Mwarp + (size_t)(dtp * DTILE + lane) * DD + ksp * KSTEP);
    }
}

__global__ void __launch_bounds__(256, 1)
fecam_score_kernel(const float* __restrict__ x,      // [32,768]
                   const float* __restrict__ mu,     // [256,768]
                   const float* __restrict__ g,      // [256,768]
                   const float* __restrict__ Minv,   // [256,768,768]
                   float* __restrict__ out)          // [32,256]
{
    extern __shared__ float smem[];
    float* sdiff = smem;                               // [32][772], e-permuted, tf32-rounded
    float* sstg  = smem + DIFF_SZ;                     // 8 x SBUF x [16][36]
    float* sred  = smem + DIFF_SZ + 8 * SBUF * WSTG;   // [8][32]

    const int c    = blockIdx.x;
    const int tid  = threadIdx.x;
    const int w    = tid >> 5;
    const int lane = tid & 31;
    const int grp  = lane >> 2;   // 0..7
    const int q    = lane & 3;    // 0..3

    // Per-warp M base: this warp's 16-row sub-slab origin (d-tile offset added per stage).
    const float* Mwarp = Minv + (size_t)c * DD * DD + (size_t)(w * WROWS) * DD;
    float* wstg = sstg + w * (SBUF * WSTG);

    // ---- Prologue: start streaming M before anything else ----
#pragma unroll
    for (int p = 0; p < LOOKAHEAD; p++)
        issue_stage_w(Mwarp, wstg, p, lane);

    // ---- Phase 1: diff[b][e] = (x[b][e]-mu[c][e])/g[c][e], TF32-rounded,
    //      stored e-permuted in smem. Batched 8 b's per step for high MLP. ----
    {
        float rcp[3], mun[3];
        int   pe[3];
#pragma unroll
        for (int i = 0; i < 3; i++) {
            int e = tid + i * 256;
            float gg = g[(size_t)c * DD + e];
            rcp[i] = 1.0f / gg;
            mun[i] = mu[(size_t)c * DD + e] * rcp[i];
            pe[i]  = PERM(e);
        }
        for (int b0 = 0; b0 < BB; b0 += 8) {
            float xv[8][3];
#pragma unroll
            for (int bb = 0; bb < 8; bb++)
#pragma unroll
                for (int i = 0; i < 3; i++)
                    xv[bb][i] = x[(b0 + bb) * DD + tid + i * 256];
#pragma unroll
            for (int bb = 0; bb < 8; bb++)
#pragma unroll
                for (int i = 0; i < 3; i++) {
                    float d = xv[bb][i] * rcp[i] - mun[i];
                    sdiff[(b0 + bb) * LDIFF + pe[i]] = __uint_as_float(f2tf(d));
                }
        }
    }
    __syncthreads();

    // Accumulators for ALL six d-tiles (ks-outer loop): warp owns rows
    // [dt*128 + w*16, +16) for every dt; acc[dt][t] = C frag for n-tile t.
    float acc[NDTILES][4][4];
#pragma unroll
    for (int dt = 0; dt < NDTILES; dt++)
#pragma unroll
        for (int t = 0; t < 4; t++)
#pragma unroll
            for (int i = 0; i < 4; i++) acc[dt][t][i] = 0.0f;

    // ---- Mainloop: ks outer (B fragments loaded ONCE per ks), dt inner ----
    for (int ks = 0; ks < KSTAGES; ks++) {
        // B fragments for all 4 n-tiles, all 4 k-steps: 8x LDS.128 (conflict-free),
        // reused across the 6 d-tiles below.
        uint4 bv[4][2];
        {
            const float* dB = sdiff + ks * KSTEP + (q << 3);
#pragma unroll
            for (int t = 0; t < 4; t++) {
                const uint4* p = (const uint4*)(dB + (t * 8 + grp) * LDIFF);
                bv[t][0] = p[0];
                bv[t][1] = p[1];
            }
        }

#pragma unroll
        for (int dt = 0; dt < NDTILES; dt++) {
            const int s = ks * NDTILES + dt;     // current stage; buf = s%6 = dt
            asm volatile("cp.async.wait_group 4;\n" ::: "memory");
            __syncwarp();

            if (s + LOOKAHEAD < NTOT) issue_stage_w(Mwarp, wstg, s + LOOKAHEAD, lane);
            else                      cp_commit();   // keep group-count invariant

            const float* stg = wstg + dt * WSTG;     // static buffer index

#pragma unroll
            for (int kk = 0; kk < 4; kk++) {
                const float* ap = stg + grp * LSTG + kk * 8 + q;
                uint32_t a0 = f2tf(ap[0]);
                uint32_t a1 = f2tf(ap[8 * LSTG]);
                uint32_t a2 = f2tf(ap[4]);
                uint32_t a3 = f2tf(ap[8 * LSTG + 4]);
#pragma unroll
                for (int t = 0; t < 4; t++) {
                    uint32_t b0, b1;
                    if      (kk == 0) { b0 = bv[t][0].x; b1 = bv[t][0].y; }
                    else if (kk == 1) { b0 = bv[t][0].z; b1 = bv[t][0].w; }
                    else if (kk == 2) { b0 = bv[t][1].x; b1 = bv[t][1].y; }
                    else              { b0 = bv[t][1].z; b1 = bv[t][1].w; }
                    mma_tf32(acc[dt][t], a0, a1, a2, a3, b0, b1);
                }
            }
        }
    }

    // ---- Epilogue: fold u[b,d] into dist partials with fp32 diff ----
    float part[8];
#pragma unroll
    for (int i = 0; i < 8; i++) part[i] = 0.0f;

#pragma unroll
    for (int dt = 0; dt < NDTILES; dt++) {
        const int dA  = dt * DTILE + (w << 4) + grp;
        const int pd0 = PERM(dA);
        const int pd1 = PERM(dA + 8);
#pragma unroll
        for (int t = 0; t < 4; t++) {
            const int b0i = t * 8 + (q << 1);
            part[2 * t]     += sdiff[b0i * LDIFF + pd0] * acc[dt][t][0]
                             + sdiff[b0i * LDIFF + pd1] * acc[dt][t][2];
            part[2 * t + 1] += sdiff[(b0i + 1) * LDIFF + pd0] * acc[dt][t][1]
                             + sdiff[(b0i + 1) * LDIFF + pd1] * acc[dt][t][3];
        }
    }

    // ---- Reduce: lanes sharing q hold the same b set; reduce over grp bits ----
#pragma unroll
    for (int i = 0; i < 8; i++) {
        part[i] += __shfl_xor_sync(0xffffffffu, part[i], 4);
        part[i] += __shfl_xor_sync(0xffffffffu, part[i], 8);
        part[i] += __shfl_xor_sync(0xffffffffu, part[i], 16);
    }
    if (lane < 4) {
#pragma unroll
        for (int t = 0; t < 4; t++) {
            sred[w * 32 + t * 8 + lane * 2]     = part[2 * t];
            sred[w * 32 + t * 8 + lane * 2 + 1] = part[2 * t + 1];
        }
    }
    __syncthreads();
    if (tid < BB) {
        float tot = 0.0f;
#pragma unroll
        for (int ww = 0; ww < 8; ww++) tot += sred[ww * 32 + tid];
        out[tid * CC + c] = -tot;   // scores[b, c]
    }
}

extern "C" void kernel_launch(void* const* d_in, const int* in_sizes, int n_in,
                              void* d_out, int out_size) {
    (void)in_sizes; (void)n_in; (void)out_size;
    const float* x  = (const float*)d_in[0];   // raw_features   [32,768]
    const float* mu = (const float*)d_in[1];   // class_means    [256,768]
    const float* g  = (const float*)d_in[2];   // class_diags    [256,768]
    const float* M  = (const float*)d_in[3];   // class_cov_invs [256,768,768]
    float* out = (float*)d_out;                // scores [32,256]

    const size_t smem_bytes = SMEM_WORDS * sizeof(float);   // ~210.4 KB
    cudaFuncSetAttribute(fecam_score_kernel,
                         cudaFuncAttributeMaxDynamicSharedMemorySize,
                         (int)smem_bytes);
    fecam_score_kernel<<<CC, 256, smem_bytes>>>(x, mu, g, M, out);
}

// round 15
// speedup vs baseline: 1.4400x; 1.0058x over previous
#include <cuda_runtime.h>
#include <cstdint>

// Problem constants
#define BB 32
#define CC 256
#define DD 768

// Tiling
#define DTILE 128                  // d rows per d-tile (16 per warp x 8 warps)
#define KSTEP 32                   // e columns per pipeline stage
#define NDTILES (DD / DTILE)       // 6
#define KSTAGES (DD / KSTEP)       // 24
#define NTOT (NDTILES * KSTAGES)   // 144 stages (order: s = ks*6 + dt)
#define SBUF 6                     // per-warp ring depth; buf == dt statically
#define LOOKAHEAD 5                // cp.async stages issued ahead
#define PFDIST 6                   // L2 prefetch distance beyond cp.async lookahead

#define WROWS 16                   // d rows per warp
#define LSTG 36                    // stage row stride (words); 36%32==4 -> conflict-free A LDS
#define WSTG (WROWS * LSTG)        // 576 words / stage / warp
#define LDIFF 772                  // diff row stride (words); 772%32==4 -> conflict-free B LDS.128

#define DIFF_SZ (BB * LDIFF)                            // 24704 words
#define SMEM_WORDS (DIFF_SZ + 8 * SBUF * WSTG + 256)    // ~210.4 KB

// e-permutation within each 32-block: groups e%4 together so that the
// {q, q+4, q+8, ...} TF32 B-fragment elements become contiguous (LDS.128-able).
#define PERM(e) (((e) & ~31) | (((e) & 3) << 3) | (((e) >> 2) & 7))

__device__ __forceinline__ uint32_t f2tf(float f) {
    uint32_t r;
    asm("cvt.rna.tf32.f32 %0, %1;\n" : "=r"(r) : "f"(f));
    return r;
}

__device__ __forceinline__ void mma_tf32(float* c,
                                         uint32_t a0, uint32_t a1, uint32_t a2, uint32_t a3,
                                         uint32_t b0, uint32_t b1) {
    asm volatile(
        "mma.sync.aligned.m16n8k8.row.col.f32.tf32.tf32.f32 "
        "{%0,%1,%2,%3}, {%4,%5,%6,%7}, {%8,%9}, {%0,%1,%2,%3};\n"
        : "+f"(c[0]), "+f"(c[1]), "+f"(c[2]), "+f"(c[3])
        : "r"(a0), "r"(a1), "r"(a2), "r"(a3), "r"(b0), "r"(b1));
}

__device__ __forceinline__ void cp_async16(float* sdst, const float* gsrc) {
    unsigned saddr = (unsigned)__cvta_generic_to_shared(sdst);
    asm volatile("cp.async.cg.shared.global [%0], [%1], 16;\n"
                 :: "r"(saddr), "l"(gsrc));
}
__device__ __forceinline__ void cp_commit() {
    asm volatile("cp.async.commit_group;\n" ::: "memory");
}
__device__ __forceinline__ void l2_prefetch(const float* p) {
    asm volatile("prefetch.global.L2 [%0];\n" :: "l"(p));
}

// Warp-private stage load: this warp's 16 rows x 32 cols of M for stage s
// (s = ks*6 + dt). Also fire-and-forget L2 prefetch of stage s+PFDIST:
// 16 lines (one per row), lanes 0-15, no smem / no tracking -> unbounded MLP.
__device__ __forceinline__ void issue_stage_w(const float* __restrict__ Mwarp,
                                              float* __restrict__ wstg,
                                              int s, int lane) {
    {
        const int dt = s % NDTILES;
        const int ks = s / NDTILES;
        const float* base = Mwarp + (size_t)(dt * DTILE) * DD + ks * KSTEP;
        float* dst = wstg + (s % SBUF) * WSTG;
#pragma unroll
        for (int j = 0; j < 4; j++) {
            int idx = lane + 32 * j;      // 0..127
            int r   = idx >> 3;           // 0..15
            int c4  = (idx & 7) << 2;     // 0,4,...,28
            cp_async16(dst + r * LSTG + c4, base + (size_t)r * DD + c4);
        }
        cp_commit();
    }
    const int spf = s + PFDIST;
    if (spf < NTOT && lane < WROWS) {
        const int dtp = spf % NDTILES;
        const int ksp = spf / NDTILES;
        l2_prefetch(Mwarp + (size_t)(dtp * DTILE + lane) * DD + ksp * KSTEP);
    }
}

__global__ void __launch_bounds__(256, 1)
fecam_score_kernel(const float* __restrict__ x,      // [32,768]
                   const float* __restrict__ mu,     // [256,768]
                   const float* __restrict__ g,      // [256,768]
                   const float* __restrict__ Minv,   // [256,768,768]
                   float* __restrict__ out)          // [32,256]
{
    extern __shared__ float smem[];
    float* sdiff = smem;                               // [32][772], e-permuted, tf32-rounded
    float* sstg  = smem + DIFF_SZ;                     // 8 x SBUF x [16][36]
    float* sred  = smem + DIFF_SZ + 8 * SBUF * WSTG;   // [8][32]

    const int c    = blockIdx.x;
    const int tid  = threadIdx.x;
    const int w    = tid >> 5;
    const int lane = tid & 31;
    const int grp  = lane >> 2;   // 0..7
    const int q    = lane & 3;    // 0..3

    // Per-warp M base: this warp's 16-row sub-slab origin (d-tile offset added per stage).
    const float* Mwarp = Minv + (size_t)c * DD * DD + (size_t)(w * WROWS) * DD;
    float* wstg = sstg + w * (SBUF * WSTG);

    // ---- Prologue: start streaming M before anything else ----
#pragma unroll
    for (int p = 0; p < LOOKAHEAD; p++)
        issue_stage_w(Mwarp, wstg, p, lane);

    // ---- Phase 1: diff[b][e] = (x[b][e]-mu[c][e])/g[c][e], TF32-rounded,
    //      stored e-permuted in smem. Batched 8 b's per step for high MLP. ----
    {
        float rcp[3], mun[3];
        int   pe[3];
#pragma unroll
        for (int i = 0; i < 3; i++) {
            int e = tid + i * 256;
            float gg = g[(size_t)c * DD + e];
            rcp[i] = 1.0f / gg;
            mun[i] = mu[(size_t)c * DD + e] * rcp[i];
            pe[i]  = PERM(e);
        }
        for (int b0 = 0; b0 < BB; b0 += 8) {
            float xv[8][3];
#pragma unroll
            for (int bb = 0; bb < 8; bb++)
#pragma unroll
                for (int i = 0; i < 3; i++)
                    xv[bb][i] = x[(b0 + bb) * DD + tid + i * 256];
#pragma unroll
            for (int bb = 0; bb < 8; bb++)
#pragma unroll
                for (int i = 0; i < 3; i++) {
                    float d = xv[bb][i] * rcp[i] - mun[i];
                    sdiff[(b0 + bb) * LDIFF + pe[i]] = __uint_as_float(f2tf(d));
                }
        }
    }
    __syncthreads();

    // Accumulators for ALL six d-tiles (ks-outer loop): warp owns rows
    // [dt*128 + w*16, +16) for every dt; acc[dt][t] = C frag for n-tile t.
    float acc[NDTILES][4][4];
#pragma unroll
    for (int dt = 0; dt < NDTILES; dt++)
#pragma unroll
        for (int t = 0; t < 4; t++)
#pragma unroll
            for (int i = 0; i < 4; i++) acc[dt][t][i] = 0.0f;

    // ---- Mainloop: ks outer (B fragments loaded ONCE per ks), dt inner ----
    for (int ks = 0; ks < KSTAGES; ks++) {
        // B fragments for all 4 n-tiles, all 4 k-steps: 8x LDS.128 (conflict-free),
        // reused across the 6 d-tiles below.
        uint4 bv[4][2];
        {
            const float* dB = sdiff + ks * KSTEP + (q << 3);
#pragma unroll
            for (int t = 0; t < 4; t++) {
                const uint4* p = (const uint4*)(dB + (t * 8 + grp) * LDIFF);
                bv[t][0] = p[0];
                bv[t][1] = p[1];
            }
        }

#pragma unroll
        for (int dt = 0; dt < NDTILES; dt++) {
            const int s = ks * NDTILES + dt;     // current stage; buf = s%6 = dt
            asm volatile("cp.async.wait_group 4;\n" ::: "memory");
            __syncwarp();

            if (s + LOOKAHEAD < NTOT) issue_stage_w(Mwarp, wstg, s + LOOKAHEAD, lane);
            else                      cp_commit();   // keep group-count invariant

            const float* stg = wstg + dt * WSTG;     // static buffer index

#pragma unroll
            for (int kk = 0; kk < 4; kk++) {
                const float* ap = stg + grp * LSTG + kk * 8 + q;
                uint32_t a0 = f2tf(ap[0]);
                uint32_t a1 = f2tf(ap[8 * LSTG]);
                uint32_t a2 = f2tf(ap[4]);
                uint32_t a3 = f2tf(ap[8 * LSTG + 4]);
#pragma unroll
                for (int t = 0; t < 4; t++) {
                    uint32_t b0, b1;
                    if      (kk == 0) { b0 = bv[t][0].x; b1 = bv[t][0].y; }
                    else if (kk == 1) { b0 = bv[t][0].z; b1 = bv[t][0].w; }
                    else if (kk == 2) { b0 = bv[t][1].x; b1 = bv[t][1].y; }
                    else              { b0 = bv[t][1].z; b1 = bv[t][1].w; }
                    mma_tf32(acc[dt][t], a0, a1, a2, a3, b0, b1);
                }
            }
        }
    }

    // ---- Epilogue: fold u[b,d] into dist partials with fp32 diff ----
    float part[8];
#pragma unroll
    for (int i = 0; i < 8; i++) part[i] = 0.0f;

#pragma unroll
    for (int dt = 0; dt < NDTILES; dt++) {
        const int dA  = dt * DTILE + (w << 4) + grp;
        const int pd0 = PERM(dA);
        const int pd1 = PERM(dA + 8);
#pragma unroll
        for (int t = 0; t < 4; t++) {
            const int b0i = t * 8 + (q << 1);
            part[2 * t]     += sdiff[b0i * LDIFF + pd0] * acc[dt][t][0]
                             + sdiff[b0i * LDIFF + pd1] * acc[dt][t][2];
            part[2 * t + 1] += sdiff[(b0i + 1) * LDIFF + pd0] * acc[dt][t][1]
                             + sdiff[(b0i + 1) * LDIFF + pd1] * acc[dt][t][3];
        }
    }

    // ---- Reduce: lanes sharing q hold the same b set; reduce over grp bits ----
#pragma unroll
    for (int i = 0; i < 8; i++) {
        part[i] += __shfl_xor_sync(0xffffffffu, part[i], 4);
        part[i] += __shfl_xor_sync(0xffffffffu, part[i], 8);
        part[i] += __shfl_xor_sync(0xffffffffu, part[i], 16);
    }
    if (lane < 4) {
#pragma unroll
        for (int t = 0; t < 4; t++) {
            sred[w * 32 + t * 8 + lane * 2]     = part[2 * t];
            sred[w * 32 + t * 8 + lane * 2 + 1] = part[2 * t + 1];
        }
    }
    __syncthreads();
    if (tid < BB) {
        float tot = 0.0f;
#pragma unroll
        for (int ww = 0; ww < 8; ww++) tot += sred[ww * 32 + tid];
        out[tid * CC + c] = -tot;   // scores[b, c]
    }
}

extern "C" void kernel_launch(void* const* d_in, const int* in_sizes, int n_in,
                              void* d_out, int out_size) {
    (void)in_sizes; (void)n_in; (void)out_size;
    const float* x  = (const float*)d_in[0];   // raw_features   [32,768]
    const float* mu = (const float*)d_in[1];   // class_means    [256,768]
    const float* g  = (const float*)d_in[2];   // class_diags    [256,768]
    const float* M  = (const float*)d_in[3];   // class_cov_invs [256,768,768]
    float* out = (float*)d_out;                // scores [32,256]

    const size_t smem_bytes = SMEM_WORDS * sizeof(float);   // ~210.4 KB
    cudaFuncSetAttribute(fecam_score_kernel,
                         cudaFuncAttributeMaxDynamicSharedMemorySize,
                         (int)smem_bytes);
    fecam_score_kernel<<<CC, 256, smem_bytes>>>(x, mu, g, M, out);
}